// round 17
// baseline (speedup 1.0000x reference)
#include <cuda_runtime.h>
#include <cuda_fp16.h>
#include <stdint.h>
#include <stddef.h>
#include <math.h>

// ---------------------------------------------------------------------------
// ChannelAttention2 on sm_103a — fp16 m16n8k16 mma.sync end-to-end (fp32
// accumulate everywhere). R17: g_qkv fp16, qkv kernel fp16 single-stage,
// win_attn phase1 fp16, V/Q staged once per window.
// ---------------------------------------------------------------------------
#define CH     192
#define NTOK   64
#define NW     576
#define NWIN   4608
#define QKVC   576
#define LTOK   36864
#define MROWS  294912

__device__ __half g_qkv[(size_t)MROWS * QKVC];   // fp16 qkv scratch (340 MB)
__device__ __half g_wpT[CH * CH];                // [j][c] = wproj[c][j]

__device__ __forceinline__ uint32_t pack_h2(float a, float b) {
    __half2 h = __floats2half2_rn(a, b);
    return *(uint32_t*)&h;
}

#define LDM_X4(R, ADDR) \
    asm volatile("ldmatrix.sync.aligned.m8n8.x4.shared.b16 {%0,%1,%2,%3}, [%4];" \
        : "=r"((R)[0]), "=r"((R)[1]), "=r"((R)[2]), "=r"((R)[3]) : "r"(ADDR))

#define MMA_F16(D, A, B0, B1) \
    asm volatile("mma.sync.aligned.m16n8k16.row.col.f32.f16.f16.f32 " \
        "{%0,%1,%2,%3}, {%4,%5,%6,%7}, {%8,%9}, {%0,%1,%2,%3};" \
        : "+f"((D)[0]), "+f"((D)[1]), "+f"((D)[2]), "+f"((D)[3]) \
        : "r"((A)[0]), "r"((A)[1]), "r"((A)[2]), "r"((A)[3]), "r"(B0), "r"(B1))

#define CP16(DST, SRC) \
    asm volatile("cp.async.cg.shared.global [%0], [%1], 16;" :: "r"(DST), "l"(SRC))
#define CP_COMMIT() asm volatile("cp.async.commit_group;")
#define CP_WAIT0()  asm volatile("cp.async.wait_group 0;")

// ---------------------------------------------------------------------------
// Kernel 0: transpose wproj -> fp16 g_wpT[j][c]  (one-off, tiny)
// ---------------------------------------------------------------------------
__global__ void wp_prep(const float* __restrict__ wproj)
{
    int i = blockIdx.x * 256 + threadIdx.x;
    if (i < CH * CH) {
        int j = i / CH, c = i - j * CH;
        g_wpT[i] = __float2half_rn(wproj[c * CH + j]);
    }
}

// ---------------------------------------------------------------------------
// Kernel 1: qkv = x @ w_qkv, all fp16 (fp32 accum). CTA tile 128(M)x96(N),
// whole K=192 staged once. 8 warps (4m x 2n), warp 32x48, 12 k16-steps.
// smem: A 128x200h (51200 B) + B^T 96x200h (38400 B) = 89600 B -> 2 CTAs/SM.
// ---------------------------------------------------------------------------
#define QK_LDA 200
#define QK_B   51200
#define QKV_SMEM 89600

__global__ void __launch_bounds__(256, 2) qkv_f16(const float* __restrict__ x,
                                                  const float* __restrict__ wq)
{
    extern __shared__ char qsc[];
    __half* As = (__half*)qsc;
    __half* Bs = (__half*)(qsc + QK_B);
    const uint32_t sb = (uint32_t)__cvta_generic_to_shared(qsc);

    const int tid  = threadIdx.x;
    const int lane = tid & 31;
    const int warp = tid >> 5;
    const int m0   = (warp >> 1) * 32;
    const int n0w  = (warp & 1) * 48;
    const int M0   = blockIdx.y * 128;
    const int N0   = blockIdx.x * 96;

    const int lr  = (lane & 7) + ((lane >> 3) & 1) * 8;
    const int hc8 = (lane >> 4) * 8;
    const int gid = lane >> 2, tig = lane & 3;

    float acc[2][6][4];
#pragma unroll
    for (int i = 0; i < 2; i++)
#pragma unroll
        for (int j = 0; j < 6; j++)
#pragma unroll
            for (int k = 0; k < 4; k++) acc[i][j][k] = 0.f;

    // stage A: x[M0..+128][0..192) fp32 -> fp16, row-major (uint2 stores)
    for (int idx = tid; idx < 128 * 48; idx += 256) {
        int m = idx / 48, q = idx - m * 48;
        float4 a = *(const float4*)&x[(size_t)(M0 + m) * CH + 4 * q];
        uint2 u = {pack_h2(a.x, a.y), pack_h2(a.z, a.w)};
        *(uint2*)&As[m * QK_LDA + 4 * q] = u;
    }
    // stage B transposed: wq[k][N0+n] -> Bs[n][k] fp16 (k-fast, conflict-free)
    for (int idx = tid; idx < 192 * 24; idx += 256) {
        int k = idx % 192, q = idx / 192;
        float4 b = *(const float4*)&wq[(size_t)k * QKVC + N0 + 4 * q];
        Bs[(4 * q + 0) * QK_LDA + k] = __float2half_rn(b.x);
        Bs[(4 * q + 1) * QK_LDA + k] = __float2half_rn(b.y);
        Bs[(4 * q + 2) * QK_LDA + k] = __float2half_rn(b.z);
        Bs[(4 * q + 3) * QK_LDA + k] = __float2half_rn(b.w);
    }
    __syncthreads();

#pragma unroll
    for (int ks = 0; ks < 12; ks++) {
        const int kch = ks * 16;
        uint32_t a[2][4], b[3][4];
#pragma unroll
        for (int mt = 0; mt < 2; mt++)
            LDM_X4(a[mt], sb + 2u * ((m0 + mt * 16 + lr) * QK_LDA + kch + hc8));
#pragma unroll
        for (int bt = 0; bt < 3; bt++)
            LDM_X4(b[bt], sb + QK_B + 2u * ((n0w + bt * 16 + lr) * QK_LDA + kch + hc8));
#pragma unroll
        for (int mt = 0; mt < 2; mt++)
#pragma unroll
            for (int nt = 0; nt < 6; nt++) {
                int bt = nt >> 1, od = nt & 1;
                MMA_F16(acc[mt][nt], a[mt], b[bt][od], b[bt][od + 2]);
            }
    }

#pragma unroll
    for (int mt = 0; mt < 2; mt++)
#pragma unroll
        for (int nt = 0; nt < 6; nt++) {
            int row = M0 + m0 + mt * 16 + gid;
            int col = N0 + n0w + nt * 8 + 2 * tig;
            __half2 h0 = __floats2half2_rn(acc[mt][nt][0], acc[mt][nt][1]);
            __half2 h1 = __floats2half2_rn(acc[mt][nt][2], acc[mt][nt][3]);
            *(__half2*)&g_qkv[(size_t)row * QKVC + col]       = h0;
            *(__half2*)&g_qkv[(size_t)(row + 8) * QKVC + col] = h1;
        }
}

// ---------------------------------------------------------------------------
// Kernel 2: fused per-window attention + projection, all fp16 MMA. 384 thr,
// 104.5 KB smem -> 2 CTAs/SM. V and Q staged ONCE per window (fp16); per
// c-half (96): KT staged, then d in 3 chunks of 64:
//   phase1 (fp16): P = KT @ Vchunk [3(c32)x4(d16)], 4 k16-steps;
//                  E = exp2(sc2*P) -> fp16; Z via smem atomics
//   phase3 (fp16): out^T += E @ Q^T [3(c32)x4(n16)], 4 k16-steps
//   epilogue: out^T *= 1/Z -> sOutH fp16; phase4 (fp16) y = out @ Wp.
// Byte layout: sOutH 64x104h | Z 128f | KT 96x72h | E 96x72h | (pad) |
//              VT 192x72h | Qh 64x200h ; WpT 192x104h overlays KT..pad.
// ---------------------------------------------------------------------------
#define NTHR    384
#define LDE     72
#define LDKT    72
#define LDVT    72
#define LDQH    200
#define LDOH    104
#define LDWH    104
#define OFF_OUTB 0                       // 13312
#define OFF_ZB   13312                   // 512
#define OFF_KTB  13824                   // 96*72*2 = 13824 -> 27648
#define OFF_EB   27648                   // 96*72*2 = 13824 -> 41472
#define OFF_WPB  OFF_KTB                 // 192*104*2 = 39936 -> 53760
#define OFF_VTB  53760                   // 192*72*2 = 27648 -> 81408
#define OFF_QHB  81408                   // 64*200*2 = 25600 -> 107008
#define ATT_SMEM 107008

__global__ void __launch_bounds__(NTHR, 2) win_attn(const float* __restrict__ bproj,
                                                    float* __restrict__ out)
{
    extern __shared__ char smc[];
    float* smZ = (float*)(smc + OFF_ZB);
    __half* KT = (__half*)(smc + OFF_KTB);
    __half* VT = (__half*)(smc + OFF_VTB);
    const uint32_t sb = (uint32_t)__cvta_generic_to_shared(smc);

    const int tid  = threadIdx.x;
    const int lane = tid & 31;
    const int warp = tid >> 5;                 // 0..11
    const int gid  = lane >> 2, tig = lane & 3;
    const int lr   = (lane & 7) + ((lane >> 3) & 1) * 8;
    const int hc8  = (lane >> 4) * 8;

    const int wi = blockIdx.x;
    const int b  = wi / NW;
    const int w  = wi - b * NW;
    const size_t rowbase = (size_t)b * LTOK + (size_t)w * NTOK;
    const size_t rbB = rowbase * (QKVC * 2);   // byte base of window in g_qkv
    const float sc2 = rsqrtf(24.0f) * 1.4426950408889634f;

    const int c1w = (warp % 3) * 32;           // phase1 c-block
    const int d1w = (warp / 3) * 16;           // phase1 d-block
    const int cb3 = (warp % 3) * 32;           // phase3 c-block (out^T rows)
    const int nb3 = (warp / 3) * 16;           // phase3 n-block
    const int mb4 = (warp / 6) * 32;           // phase4 n-block
    const int jb4 = (warp % 6) * 32;           // phase4 j-block

    // ---- Qh: pure cp.async copy (Q rows are contiguous fp16)
    for (int idx = tid; idx < 64 * 24; idx += NTHR) {
        int n = idx / 24, q = idx - n * 24;
        CP16(sb + OFF_QHB + n * 400 + 16 * q,
             (const char*)g_qkv + rbB + (size_t)n * 1152 + 16 * q);
    }
    CP_COMMIT();
    // ---- VT: transpose-stage V (once per window), n-fast conflict-free
    for (int idx = tid; idx < 24 * 64; idx += NTHR) {
        int n = idx & 63, q = idx >> 6;        // q: 0..23 (8 d per iter)
        uint4 u = *(const uint4*)((const char*)g_qkv + rbB
                                  + (size_t)n * 1152 + 768 + 16 * q);
        const __half* s = (const __half*)&u;
#pragma unroll
        for (int i = 0; i < 8; i++)
            VT[(8 * q + i) * LDVT + n] = s[i];
    }

    for (int h = 0; h < 2; h++) {
        const int c0 = h * 96;

        // ---- KT: transpose-stage K half, zero Z
        for (int idx = tid; idx < 12 * 64; idx += NTHR) {
            int n = idx & 63, q = idx >> 6;    // q: 0..11
            uint4 u = *(const uint4*)((const char*)g_qkv + rbB
                        + (size_t)n * 1152 + 384 + 2 * c0 + 16 * q);
            const __half* s = (const __half*)&u;
#pragma unroll
            for (int i = 0; i < 8; i++)
                KT[(8 * q + i) * LDKT + n] = s[i];
        }
        if (tid < 96) smZ[tid] = 0.f;
        if (h == 0) CP_WAIT0();                // Qh arrived
        __syncthreads();

        float o[2][2][4];                       // out^T acc: 32c x 16n
#pragma unroll
        for (int i = 0; i < 2; i++)
#pragma unroll
            for (int j = 0; j < 2; j++)
#pragma unroll
                for (int k = 0; k < 4; k++) o[i][j][k] = 0.f;

        for (int dc = 0; dc < 3; dc++) {
            const int d0 = dc * 64;

            // ---- phase1 (fp16): P = KT @ Vchunk, 3(c=32) x 4(d=16), 4 k16
            {
                float p[2][2][4];
#pragma unroll
                for (int i = 0; i < 2; i++)
#pragma unroll
                    for (int j = 0; j < 2; j++)
#pragma unroll
                        for (int k = 0; k < 4; k++) p[i][j][k] = 0.f;

#pragma unroll
                for (int ks = 0; ks < 4; ks++) {
                    const int kch = ks * 16;
                    uint32_t aK[2][4], bV[4];
#pragma unroll
                    for (int mt = 0; mt < 2; mt++)
                        LDM_X4(aK[mt], sb + OFF_KTB
                               + 2u * ((c1w + mt * 16 + lr) * LDKT + kch + hc8));
                    LDM_X4(bV, sb + OFF_VTB
                               + 2u * ((d0 + d1w + lr) * LDVT + kch + hc8));
#pragma unroll
                    for (int mt = 0; mt < 2; mt++)
#pragma unroll
                        for (int nt = 0; nt < 2; nt++)
                            MMA_F16(p[mt][nt], aK[mt], bV[nt], bV[nt + 2]);
                }
#pragma unroll
                for (int mt = 0; mt < 2; mt++) {
                    float slo = 0.f, shi = 0.f;
                    int r = c1w + mt * 16 + gid;
#pragma unroll
                    for (int nt = 0; nt < 2; nt++) {
                        float e0 = exp2f(p[mt][nt][0] * sc2);
                        float e1 = exp2f(p[mt][nt][1] * sc2);
                        float e2 = exp2f(p[mt][nt][2] * sc2);
                        float e3 = exp2f(p[mt][nt][3] * sc2);
                        slo += e0 + e1;
                        shi += e2 + e3;
                        int c = d1w + nt * 8 + 2 * tig;
                        *(uint32_t*)(smc + OFF_EB + 2 * (r * LDE + c))
                            = pack_h2(e0, e1);
                        *(uint32_t*)(smc + OFF_EB + 2 * ((r + 8) * LDE + c))
                            = pack_h2(e2, e3);
                    }
                    slo += __shfl_xor_sync(0xffffffffu, slo, 1);
                    slo += __shfl_xor_sync(0xffffffffu, slo, 2);
                    shi += __shfl_xor_sync(0xffffffffu, shi, 1);
                    shi += __shfl_xor_sync(0xffffffffu, shi, 2);
                    if (tig == 0) {
                        atomicAdd(&smZ[r],     slo);
                        atomicAdd(&smZ[r + 8], shi);
                    }
                }
            }
            __syncthreads();

            // ---- phase3 (fp16): out^T += E @ Q^T, 3(c=32) x 4(n=16), 4 k16
#pragma unroll
            for (int ks = 0; ks < 4; ks++) {
                const int kch = ks * 16;
                uint32_t aE[2][4], bQ[4];
#pragma unroll
                for (int mt = 0; mt < 2; mt++)
                    LDM_X4(aE[mt], sb + OFF_EB
                           + 2u * ((cb3 + mt * 16 + lr) * LDE + kch + hc8));
                LDM_X4(bQ, sb + OFF_QHB
                           + 2u * ((nb3 + lr) * LDQH + d0 + kch + hc8));
#pragma unroll
                for (int mt = 0; mt < 2; mt++)
#pragma unroll
                    for (int nt = 0; nt < 2; nt++)
                        MMA_F16(o[mt][nt], aE[mt], bQ[nt], bQ[nt + 2]);
            }
            __syncthreads();
        }

        // ---- stage WpT half via cp.async (overlays KT+E; both dead now)
        for (int idx = tid; idx < 192 * 12; idx += NTHR) {
            int j = idx / 12, q = idx - j * 12;
            CP16(sb + OFF_WPB + j * (LDWH * 2) + 16 * q,
                 (const char*)g_wpT + j * (CH * 2) + 2 * c0 + 16 * q);
        }
        CP_COMMIT();

        // ---- phase3 epilogue: 1/Z, transpose-store -> sOutH[n][c] fp16
#pragma unroll
        for (int mt = 0; mt < 2; mt++) {
            int c = cb3 + mt * 16 + gid;
            float iz0 = 1.0f / smZ[c];
            float iz1 = 1.0f / smZ[c + 8];
#pragma unroll
            for (int nt = 0; nt < 2; nt++) {
                int n = nb3 + nt * 8 + 2 * tig;
                __half* O = (__half*)(smc + OFF_OUTB);
                O[n * LDOH + c]           = __float2half_rn(o[mt][nt][0] * iz0);
                O[(n + 1) * LDOH + c]     = __float2half_rn(o[mt][nt][1] * iz0);
                O[n * LDOH + c + 8]       = __float2half_rn(o[mt][nt][2] * iz1);
                O[(n + 1) * LDOH + c + 8] = __float2half_rn(o[mt][nt][3] * iz1);
            }
        }
        CP_WAIT0();
        __syncthreads();   // sOutH + WpT ready

        // ---- phase4 (fp16): y_half = out @ Wp-half, 2(n=32) x 6(j=32), k16
        {
            float yacc[2][4][4];
#pragma unroll
            for (int i = 0; i < 2; i++)
#pragma unroll
                for (int j = 0; j < 4; j++)
#pragma unroll
                    for (int k = 0; k < 4; k++) yacc[i][j][k] = 0.f;

#pragma unroll
            for (int ks = 0; ks < 6; ks++) {
                const int kch = ks * 16;
                uint32_t aO[2][4], bW[2][4];
#pragma unroll
                for (int mt = 0; mt < 2; mt++)
                    LDM_X4(aO[mt], sb + OFF_OUTB
                           + 2u * ((mb4 + mt * 16 + lr) * LDOH + kch + hc8));
#pragma unroll
                for (int bt = 0; bt < 2; bt++)
                    LDM_X4(bW[bt], sb + OFF_WPB
                           + 2u * ((jb4 + bt * 16 + lr) * LDWH + kch + hc8));
#pragma unroll
                for (int mt = 0; mt < 2; mt++)
#pragma unroll
                    for (int nt = 0; nt < 4; nt++) {
                        int bt = nt >> 1, od = nt & 1;
                        MMA_F16(yacc[mt][nt], aO[mt], bW[bt][od], bW[bt][od + 2]);
                    }
            }

#pragma unroll
            for (int mt = 0; mt < 2; mt++) {
                int n = mb4 + mt * 16 + gid;
                float* base0 = &out[(rowbase + n) * CH];
                float* base8 = &out[(rowbase + n + 8) * CH];
                if (h == 0) {
#pragma unroll
                    for (int nt = 0; nt < 4; nt++) {
                        int j = jb4 + nt * 8 + 2 * tig;
                        float b0 = __ldg(&bproj[j]), b1 = __ldg(&bproj[j + 1]);
                        float2 v0 = {yacc[mt][nt][0] + b0, yacc[mt][nt][1] + b1};
                        float2 v1 = {yacc[mt][nt][2] + b0, yacc[mt][nt][3] + b1};
                        *(float2*)&base0[j] = v0;
                        *(float2*)&base8[j] = v1;
                    }
                } else {
#pragma unroll
                    for (int nt = 0; nt < 4; nt++) {
                        int j = jb4 + nt * 8 + 2 * tig;
                        asm volatile("red.global.add.f32 [%0], %1;" ::
                            "l"(&base0[j]), "f"(yacc[mt][nt][0]) : "memory");
                        asm volatile("red.global.add.f32 [%0], %1;" ::
                            "l"(&base0[j + 1]), "f"(yacc[mt][nt][1]) : "memory");
                        asm volatile("red.global.add.f32 [%0], %1;" ::
                            "l"(&base8[j]), "f"(yacc[mt][nt][2]) : "memory");
                        asm volatile("red.global.add.f32 [%0], %1;" ::
                            "l"(&base8[j + 1]), "f"(yacc[mt][nt][3]) : "memory");
                    }
                }
            }
        }
        __syncthreads();   // Wp/KT region restaged next half
    }
}

// ---------------------------------------------------------------------------
extern "C" void kernel_launch(void* const* d_in, const int* in_sizes, int n_in,
                              void* d_out, int out_size)
{
    (void)in_sizes; (void)n_in; (void)out_size;
    const float* x     = (const float*)d_in[0];
    const float* wqkv  = (const float*)d_in[1];
    const float* wproj = (const float*)d_in[2];
    const float* bproj = (const float*)d_in[3];
    float* out = (float*)d_out;

    cudaFuncSetAttribute(qkv_f16, cudaFuncAttributeMaxDynamicSharedMemorySize,
                         QKV_SMEM);
    cudaFuncSetAttribute(win_attn, cudaFuncAttributeMaxDynamicSharedMemorySize,
                         ATT_SMEM);

    wp_prep<<<(CH * CH + 255) / 256, 256>>>(wproj);
    dim3 g1(QKVC / 96, MROWS / 128);   // 6 x 2304
    qkv_f16<<<g1, 256, QKV_SMEM>>>(x, wqkv);
    win_attn<<<NWIN, NTHR, ATT_SMEM>>>(bproj, out);
}